// round 12
// baseline (speedup 1.0000x reference)
#include <cuda_runtime.h>
#include <math.h>

#define B   64
#define T   4096
#define QS  1024
#define KS  1024
#define QSPLIT 16             // q-chunks for split-K mids
#define QCHUNK (QS / QSPLIT)  // 64
#define T_PER_BLOCK 64           // rows per scores block (8 warps x 8 rows)
#define NBLK (T / T_PER_BLOCK)   // 64 t-blocks per batch row

// Scratch (no allocations allowed)
__device__ float g_mids[B * KS];               // 256 KB
__device__ float g_part[QSPLIT * B * KS];      // 4 MB split-K partials
__device__ float g_scores[B * T];              // 1 MB (holds exp(tanh)·mask)
__device__ float g_psum[B * NBLK];             // per-block partial sums

// ---------------------------------------------------------------------------
// Kernel 1a: split-K partial GEMM for mids.
// ---------------------------------------------------------------------------
#define KC 32
__global__ void mids_partial_kernel(const float* __restrict__ query,
                                    const float* __restrict__ W) {
    __shared__ float sA[64][KC + 1];   // query tile  [b][q]
    __shared__ float sB[64][KC + 1];   // W tile      [k][q]

    const int k0  = blockIdx.x * 64;
    const int qc  = blockIdx.y;
    const int tid = threadIdx.x;          // 0..255
    const int tx  = tid & 15;
    const int ty  = tid >> 4;

    float acc[4][4];
#pragma unroll
    for (int i = 0; i < 4; i++)
#pragma unroll
        for (int j = 0; j < 4; j++) acc[i][j] = 0.f;

    const int qbase = qc * QCHUNK;
    for (int q0 = qbase; q0 < qbase + QCHUNK; q0 += KC) {
#pragma unroll
        for (int s = 0; s < 8; s++) {
            int idx = tid + s * 256;
            int r = idx >> 5;
            int c = idx & 31;
            sA[r][c] = query[r * QS + q0 + c];
            sB[r][c] = W[(size_t)(k0 + r) * QS + q0 + c];
        }
        __syncthreads();

#pragma unroll
        for (int qq = 0; qq < KC; qq++) {
            float a[4], bb[4];
#pragma unroll
            for (int i = 0; i < 4; i++) a[i]  = sA[ty * 4 + i][qq];
#pragma unroll
            for (int j = 0; j < 4; j++) bb[j] = sB[tx * 4 + j][qq];
#pragma unroll
            for (int i = 0; i < 4; i++)
#pragma unroll
                for (int j = 0; j < 4; j++) acc[i][j] += a[i] * bb[j];
        }
        __syncthreads();
    }

    float* dst = g_part + (size_t)qc * (B * KS);
#pragma unroll
    for (int i = 0; i < 4; i++) {
        int b = ty * 4 + i;
#pragma unroll
        for (int j = 0; j < 4; j++) {
            int k = k0 + tx * 4 + j;
            dst[b * KS + k] = acc[i][j];
        }
    }
}

// ---------------------------------------------------------------------------
// Kernel 1b: reduce split-K partials into g_mids. PDL-dependent on 1a.
// ---------------------------------------------------------------------------
__global__ void mids_reduce_kernel() {
    const int i = blockIdx.x * blockDim.x + threadIdx.x;
    cudaGridDependencySynchronize();
    const float4* p = (const float4*)g_part;
    float4 s = p[i];
#pragma unroll
    for (int qc = 1; qc < QSPLIT; qc++) {
        float4 v = p[(size_t)qc * (B * KS / 4) + i];
        s.x += v.x; s.y += v.y; s.z += v.z; s.w += v.w;
    }
    ((float4*)g_mids)[i] = s;
}

// ---------------------------------------------------------------------------
// Kernel 2: e[b,t] = exp(tanh(key[b,t,:] . mids[b,:] + bias)) * mask[b,t]
// plus per-block partial sum (deterministic, no atomics).
// Block shape FROZEN at 256 threads / 8 warps (the 7.15 TB/s form).
// vs R11: T_PER_BLOCK 32 -> 64 (8 row-iterations per warp, 4096 blocks),
// halving prologue/epilogue count at identical per-SM warp population.
// ---------------------------------------------------------------------------
__global__ void scores_kernel(const float* __restrict__ key,
                              const float* __restrict__ mask,
                              const float* __restrict__ bias) {
    __shared__ float s_mids[KS];
    __shared__ float s_wsum[8];
    const int b = blockIdx.y;

    cudaGridDependencySynchronize();     // g_mids ready after this

    // vectorized prologue: one LDG.128 + STS.128 per thread (256 float4 total)
    {
        const float4* gm4 = (const float4*)(g_mids + b * KS);
        ((float4*)s_mids)[threadIdx.x] = gm4[threadIdx.x];
    }
    __syncthreads();

    const float bias0 = bias[0];
    const int warp = threadIdx.x >> 5;
    const int lane = threadIdx.x & 31;
    const int t0   = blockIdx.x * T_PER_BLOCK;
    const float4* smv = (const float4*)s_mids;

    float wsum = 0.f;   // lane-0 accumulator of this warp's e values

#pragma unroll
    for (int ti = warp; ti < T_PER_BLOCK; ti += 8) {
        const int t = t0 + ti;
        // hoisted: overlaps the 8 float4 loads + reduce below
        float mval = (lane == 0) ? mask[b * T + t] : 0.f;

        const float4* row =
            (const float4*)(key + ((size_t)b * T + t) * (size_t)KS);
        float acc = 0.f;
#pragma unroll
        for (int i = 0; i < 8; i++) {
            float4 kv = __ldcs(row + lane + i * 32);   // streaming: evict-first
            float4 mv = smv[lane + i * 32];
            acc += kv.x * mv.x + kv.y * mv.y + kv.z * mv.z + kv.w * mv.w;
        }
#pragma unroll
        for (int o = 16; o > 0; o >>= 1)
            acc += __shfl_xor_sync(0xffffffffu, acc, o);
        if (lane == 0) {
            float e = __expf(tanhf(acc + bias0)) * mval;
            g_scores[b * T + t] = e;
            wsum += e;
        }
    }

    if (lane == 0) s_wsum[warp] = wsum;
    __syncthreads();
    if (threadIdx.x == 0) {
        float s = 0.f;
#pragma unroll
        for (int w = 0; w < 8; w++) s += s_wsum[w];
        g_psum[b * NBLK + blockIdx.x] = s;
    }
}

// ---------------------------------------------------------------------------
// Kernel 3: normalize. grid (4, B) x 256 threads, barrier-free: every warp
// redundantly reduces the 64 L2-resident psums via shfl (2 loads/lane);
// no smem, no __syncthreads; the v-load overlaps the reduction.
// ---------------------------------------------------------------------------
__global__ void normalize_kernel(float* __restrict__ out) {
    const int b    = blockIdx.y;
    const int tid  = threadIdx.x;          // 0..255
    const int lane = tid & 31;

    cudaGridDependencySynchronize();

    // element this thread owns (independent of the reduction -> overlaps)
    const int idx = blockIdx.x * 256 + tid;   // float4 index within row b
    const float4* src = (const float4*)(g_scores + b * T);
    float4 v = src[idx];

    // per-warp redundant reduction of the 64 per-block partials
    float s = 0.f;
#pragma unroll
    for (int i = 0; i < 2; i++)
        s += g_psum[b * NBLK + lane + i * 32];
#pragma unroll
    for (int o = 16; o > 0; o >>= 1)
        s += __shfl_xor_sync(0xffffffffu, s, o);
    const float inv = 1.0f / s;

    float4* dst = (float4*)(out + b * T);
    v.x *= inv; v.y *= inv; v.z *= inv; v.w *= inv;
    dst[idx] = v;
}

// ---------------------------------------------------------------------------
// Host: PDL launches.
// ---------------------------------------------------------------------------
template <typename K, typename... Args>
static inline void launch_pdl(dim3 grid, dim3 block, K kern, Args... args) {
    cudaLaunchConfig_t cfg = {};
    cudaLaunchAttribute attr[1];
    attr[0].id = cudaLaunchAttributeProgrammaticStreamSerialization;
    attr[0].val.programmaticStreamSerializationAllowed = 1;
    cfg.gridDim = grid;
    cfg.blockDim = block;
    cfg.dynamicSmemBytes = 0;
    cfg.stream = 0;
    cfg.attrs = attr;
    cfg.numAttrs = 1;
    cudaLaunchKernelEx(&cfg, kern, args...);
}

extern "C" void kernel_launch(void* const* d_in, const int* in_sizes, int n_in,
                              void* d_out, int out_size) {
    const float* query = (const float*)d_in[0];   // [B, QS]
    const float* key   = (const float*)d_in[1];   // [B, T, KS]
    const float* mask  = (const float*)d_in[2];   // [B, T]
    const float* W     = (const float*)d_in[3];   // [KS, QS]
    const float* bias  = (const float*)d_in[4];   // [1]
    float* out = (float*)d_out;                   // [B, T]

    dim3 grid1(KS / 64, QSPLIT);
    mids_partial_kernel<<<grid1, 256>>>(query, W);

    launch_pdl(dim3((B * KS / 4) / 256), dim3(256), mids_reduce_kernel);

    launch_pdl(dim3(NBLK, B), dim3(256), scores_kernel, key, mask, bias);

    launch_pdl(dim3(T / 4 / 256, B), dim3(256), normalize_kernel, out);
}

// round 13
// speedup vs baseline: 1.0107x; 1.0107x over previous
#include <cuda_runtime.h>
#include <math.h>

#define B   64
#define T   4096
#define QS  1024
#define KS  1024
#define QSPLIT 16             // q-chunks for split-K mids
#define QCHUNK (QS / QSPLIT)  // 64
#define T_PER_BLOCK 32
#define NBLK (T / T_PER_BLOCK)   // 128 t-blocks per batch row

// Scratch (no allocations allowed)
__device__ float g_mids[B * KS];               // 256 KB
__device__ float g_part[QSPLIT * B * KS];      // 4 MB split-K partials
__device__ float g_scores[B * T];              // 1 MB (holds exp(tanh)·mask)
__device__ float g_psum[B * NBLK];             // 32 KB per-block partial sums

// ---------------------------------------------------------------------------
// Kernel 1a: split-K partial GEMM for mids.
// ---------------------------------------------------------------------------
#define KC 32
__global__ void mids_partial_kernel(const float* __restrict__ query,
                                    const float* __restrict__ W) {
    __shared__ float sA[64][KC + 1];   // query tile  [b][q]
    __shared__ float sB[64][KC + 1];   // W tile      [k][q]

    const int k0  = blockIdx.x * 64;
    const int qc  = blockIdx.y;
    const int tid = threadIdx.x;          // 0..255
    const int tx  = tid & 15;
    const int ty  = tid >> 4;

    float acc[4][4];
#pragma unroll
    for (int i = 0; i < 4; i++)
#pragma unroll
        for (int j = 0; j < 4; j++) acc[i][j] = 0.f;

    const int qbase = qc * QCHUNK;
    for (int q0 = qbase; q0 < qbase + QCHUNK; q0 += KC) {
#pragma unroll
        for (int s = 0; s < 8; s++) {
            int idx = tid + s * 256;
            int r = idx >> 5;
            int c = idx & 31;
            sA[r][c] = query[r * QS + q0 + c];
            sB[r][c] = W[(size_t)(k0 + r) * QS + q0 + c];
        }
        __syncthreads();

#pragma unroll
        for (int qq = 0; qq < KC; qq++) {
            float a[4], bb[4];
#pragma unroll
            for (int i = 0; i < 4; i++) a[i]  = sA[ty * 4 + i][qq];
#pragma unroll
            for (int j = 0; j < 4; j++) bb[j] = sB[tx * 4 + j][qq];
#pragma unroll
            for (int i = 0; i < 4; i++)
#pragma unroll
                for (int j = 0; j < 4; j++) acc[i][j] += a[i] * bb[j];
        }
        __syncthreads();
    }

    float* dst = g_part + (size_t)qc * (B * KS);
#pragma unroll
    for (int i = 0; i < 4; i++) {
        int b = ty * 4 + i;
#pragma unroll
        for (int j = 0; j < 4; j++) {
            int k = k0 + tx * 4 + j;
            dst[b * KS + k] = acc[i][j];
        }
    }
}

// ---------------------------------------------------------------------------
// Kernel 1b: reduce split-K partials into g_mids. PDL-dependent on 1a.
// ---------------------------------------------------------------------------
__global__ void mids_reduce_kernel() {
    const int i = blockIdx.x * blockDim.x + threadIdx.x;
    cudaGridDependencySynchronize();
    const float4* p = (const float4*)g_part;
    float4 s = p[i];
#pragma unroll
    for (int qc = 1; qc < QSPLIT; qc++) {
        float4 v = p[(size_t)qc * (B * KS / 4) + i];
        s.x += v.x; s.y += v.y; s.z += v.z; s.w += v.w;
    }
    ((float4*)g_mids)[i] = s;
}

// ---------------------------------------------------------------------------
// Kernel 2: e[b,t] = exp(tanh(key[b,t,:] . mids[b,:] + bias)) * mask[b,t]
// plus per-block partial sum (deterministic, no atomics).
// FINAL shape: 256 threads / 8 warps / 8192 blocks (measured 7.15 TB/s).
// Four independent reshaping attempts (ILP, persistent, 512-thr, 64-row)
// all regressed — the 8192-block stream is what keeps the LSU queues full
// across block drain/fill transitions. Do not modify.
// ---------------------------------------------------------------------------
__global__ void scores_kernel(const float* __restrict__ key,
                              const float* __restrict__ mask,
                              const float* __restrict__ bias) {
    __shared__ float s_mids[KS];
    __shared__ float s_wsum[8];
    const int b = blockIdx.y;

    cudaGridDependencySynchronize();     // g_mids ready after this

    // vectorized prologue: one LDG.128 + STS.128 per thread (256 float4 total)
    {
        const float4* gm4 = (const float4*)(g_mids + b * KS);
        ((float4*)s_mids)[threadIdx.x] = gm4[threadIdx.x];
    }
    __syncthreads();

    const float bias0 = bias[0];
    const int warp = threadIdx.x >> 5;
    const int lane = threadIdx.x & 31;
    const int t0   = blockIdx.x * T_PER_BLOCK;
    const float4* smv = (const float4*)s_mids;

    float wsum = 0.f;   // lane-0 accumulator of this warp's e values

#pragma unroll
    for (int ti = warp; ti < T_PER_BLOCK; ti += 8) {
        const int t = t0 + ti;
        // hoisted: overlaps the 8 float4 loads + reduce below
        float mval = (lane == 0) ? mask[b * T + t] : 0.f;

        const float4* row =
            (const float4*)(key + ((size_t)b * T + t) * (size_t)KS);
        float acc = 0.f;
#pragma unroll
        for (int i = 0; i < 8; i++) {
            float4 kv = __ldcs(row + lane + i * 32);   // streaming: evict-first
            float4 mv = smv[lane + i * 32];
            acc += kv.x * mv.x + kv.y * mv.y + kv.z * mv.z + kv.w * mv.w;
        }
#pragma unroll
        for (int o = 16; o > 0; o >>= 1)
            acc += __shfl_xor_sync(0xffffffffu, acc, o);
        if (lane == 0) {
            float e = __expf(tanhf(acc + bias0)) * mval;
            g_scores[b * T + t] = e;
            wsum += e;
        }
    }

    if (lane == 0) s_wsum[warp] = wsum;
    __syncthreads();
    if (threadIdx.x == 0) {
        float s = 0.f;
#pragma unroll
        for (int w = 0; w < 8; w++) s += s_wsum[w];
        g_psum[b * NBLK + blockIdx.x] = s;
    }
}

// ---------------------------------------------------------------------------
// Kernel 3: normalize. grid (4, B) x 256 threads, barrier-free: every warp
// redundantly reduces the 128 L2-resident psums via shfl (4 loads/lane);
// no smem, no __syncthreads; the v-load overlaps the reduction.
// ---------------------------------------------------------------------------
__global__ void normalize_kernel(float* __restrict__ out) {
    const int b    = blockIdx.y;
    const int tid  = threadIdx.x;          // 0..255
    const int lane = tid & 31;

    cudaGridDependencySynchronize();

    // element this thread owns (independent of the reduction -> overlaps)
    const int idx = blockIdx.x * 256 + tid;   // float4 index within row b
    const float4* src = (const float4*)(g_scores + b * T);
    float4 v = src[idx];

    // per-warp redundant reduction of the 128 per-block partials
    float s = 0.f;
#pragma unroll
    for (int i = 0; i < 4; i++)
        s += g_psum[b * NBLK + lane + i * 32];
#pragma unroll
    for (int o = 16; o > 0; o >>= 1)
        s += __shfl_xor_sync(0xffffffffu, s, o);
    const float inv = 1.0f / s;

    float4* dst = (float4*)(out + b * T);
    v.x *= inv; v.y *= inv; v.z *= inv; v.w *= inv;
    dst[idx] = v;
}

// ---------------------------------------------------------------------------
// Host: PDL launches.
// ---------------------------------------------------------------------------
template <typename K, typename... Args>
static inline void launch_pdl(dim3 grid, dim3 block, K kern, Args... args) {
    cudaLaunchConfig_t cfg = {};
    cudaLaunchAttribute attr[1];
    attr[0].id = cudaLaunchAttributeProgrammaticStreamSerialization;
    attr[0].val.programmaticStreamSerializationAllowed = 1;
    cfg.gridDim = grid;
    cfg.blockDim = block;
    cfg.dynamicSmemBytes = 0;
    cfg.stream = 0;
    cfg.attrs = attr;
    cfg.numAttrs = 1;
    cudaLaunchKernelEx(&cfg, kern, args...);
}

extern "C" void kernel_launch(void* const* d_in, const int* in_sizes, int n_in,
                              void* d_out, int out_size) {
    const float* query = (const float*)d_in[0];   // [B, QS]
    const float* key   = (const float*)d_in[1];   // [B, T, KS]
    const float* mask  = (const float*)d_in[2];   // [B, T]
    const float* W     = (const float*)d_in[3];   // [KS, QS]
    const float* bias  = (const float*)d_in[4];   // [1]
    float* out = (float*)d_out;                   // [B, T]

    dim3 grid1(KS / 64, QSPLIT);
    mids_partial_kernel<<<grid1, 256>>>(query, W);

    launch_pdl(dim3((B * KS / 4) / 256), dim3(256), mids_reduce_kernel);

    launch_pdl(dim3(NBLK, B), dim3(256), scores_kernel, key, mask, bias);

    launch_pdl(dim3(T / 4 / 256, B), dim3(256), normalize_kernel, out);
}

// round 14
// speedup vs baseline: 1.0204x; 1.0096x over previous
#include <cuda_runtime.h>
#include <math.h>

#define B   64
#define T   4096
#define QS  1024
#define KS  1024
#define QSPLIT 16             // q-chunks for split-K mids
#define QCHUNK (QS / QSPLIT)  // 64
#define T_PER_BLOCK 32
#define NBLK (T / T_PER_BLOCK)   // 128 t-blocks per batch row

// Scratch (no allocations allowed)
__device__ float g_mids[B * KS];               // 256 KB
__device__ float g_part[QSPLIT * B * KS];      // 4 MB split-K partials
__device__ float g_scores[B * T];              // 1 MB (holds exp(tanh)·mask)
__device__ float g_psum[B * NBLK];             // 32 KB per-block partial sums

// HW tanh (sm_75+): single MUFU-class op, max err ~1e-5 (threshold is 1e-3).
__device__ __forceinline__ float fast_tanh(float x) {
    float y;
    asm("tanh.approx.f32 %0, %1;" : "=f"(y) : "f"(x));
    return y;
}

// ---------------------------------------------------------------------------
// Kernel 1a: split-K partial GEMM for mids.
// ---------------------------------------------------------------------------
#define KC 32
__global__ void mids_partial_kernel(const float* __restrict__ query,
                                    const float* __restrict__ W) {
    __shared__ float sA[64][KC + 1];   // query tile  [b][q]
    __shared__ float sB[64][KC + 1];   // W tile      [k][q]

    const int k0  = blockIdx.x * 64;
    const int qc  = blockIdx.y;
    const int tid = threadIdx.x;          // 0..255
    const int tx  = tid & 15;
    const int ty  = tid >> 4;

    float acc[4][4];
#pragma unroll
    for (int i = 0; i < 4; i++)
#pragma unroll
        for (int j = 0; j < 4; j++) acc[i][j] = 0.f;

    const int qbase = qc * QCHUNK;
    for (int q0 = qbase; q0 < qbase + QCHUNK; q0 += KC) {
#pragma unroll
        for (int s = 0; s < 8; s++) {
            int idx = tid + s * 256;
            int r = idx >> 5;
            int c = idx & 31;
            sA[r][c] = query[r * QS + q0 + c];
            sB[r][c] = W[(size_t)(k0 + r) * QS + q0 + c];
        }
        __syncthreads();

#pragma unroll
        for (int qq = 0; qq < KC; qq++) {
            float a[4], bb[4];
#pragma unroll
            for (int i = 0; i < 4; i++) a[i]  = sA[ty * 4 + i][qq];
#pragma unroll
            for (int j = 0; j < 4; j++) bb[j] = sB[tx * 4 + j][qq];
#pragma unroll
            for (int i = 0; i < 4; i++)
#pragma unroll
                for (int j = 0; j < 4; j++) acc[i][j] += a[i] * bb[j];
        }
        __syncthreads();
    }

    float* dst = g_part + (size_t)qc * (B * KS);
#pragma unroll
    for (int i = 0; i < 4; i++) {
        int b = ty * 4 + i;
#pragma unroll
        for (int j = 0; j < 4; j++) {
            int k = k0 + tx * 4 + j;
            dst[b * KS + k] = acc[i][j];
        }
    }
}

// ---------------------------------------------------------------------------
// Kernel 1b: reduce split-K partials into g_mids. PDL-dependent on 1a.
// ---------------------------------------------------------------------------
__global__ void mids_reduce_kernel() {
    const int i = blockIdx.x * blockDim.x + threadIdx.x;
    cudaGridDependencySynchronize();
    const float4* p = (const float4*)g_part;
    float4 s = p[i];
#pragma unroll
    for (int qc = 1; qc < QSPLIT; qc++) {
        float4 v = p[(size_t)qc * (B * KS / 4) + i];
        s.x += v.x; s.y += v.y; s.z += v.z; s.w += v.w;
    }
    ((float4*)g_mids)[i] = s;
}

// ---------------------------------------------------------------------------
// Kernel 2: e[b,t] = exp(tanh(key[b,t,:] . mids[b,:] + bias)) * mask[b,t]
// plus per-block partial sum (deterministic, no atomics).
// FINAL shape: 256 threads / 8 warps / 8192 blocks (measured 7.15 TB/s).
// Four reshaping attempts (ILP, persistent, 512-thr, 64-row) all regressed.
// Only change vs the 163.6us best: tanhf -> HW tanh.approx (shorter row-tail
// dependency chain).
// ---------------------------------------------------------------------------
__global__ void scores_kernel(const float* __restrict__ key,
                              const float* __restrict__ mask,
                              const float* __restrict__ bias) {
    __shared__ float s_mids[KS];
    __shared__ float s_wsum[8];
    const int b = blockIdx.y;

    cudaGridDependencySynchronize();     // g_mids ready after this

    // vectorized prologue: one LDG.128 + STS.128 per thread (256 float4 total)
    {
        const float4* gm4 = (const float4*)(g_mids + b * KS);
        ((float4*)s_mids)[threadIdx.x] = gm4[threadIdx.x];
    }
    __syncthreads();

    const float bias0 = bias[0];
    const int warp = threadIdx.x >> 5;
    const int lane = threadIdx.x & 31;
    const int t0   = blockIdx.x * T_PER_BLOCK;
    const float4* smv = (const float4*)s_mids;

    float wsum = 0.f;   // lane-0 accumulator of this warp's e values

#pragma unroll
    for (int ti = warp; ti < T_PER_BLOCK; ti += 8) {
        const int t = t0 + ti;
        // hoisted: overlaps the 8 float4 loads + reduce below
        float mval = (lane == 0) ? mask[b * T + t] : 0.f;

        const float4* row =
            (const float4*)(key + ((size_t)b * T + t) * (size_t)KS);
        float acc = 0.f;
#pragma unroll
        for (int i = 0; i < 8; i++) {
            float4 kv = __ldcs(row + lane + i * 32);   // streaming: evict-first
            float4 mv = smv[lane + i * 32];
            acc += kv.x * mv.x + kv.y * mv.y + kv.z * mv.z + kv.w * mv.w;
        }
#pragma unroll
        for (int o = 16; o > 0; o >>= 1)
            acc += __shfl_xor_sync(0xffffffffu, acc, o);
        if (lane == 0) {
            float e = __expf(fast_tanh(acc + bias0)) * mval;
            g_scores[b * T + t] = e;
            wsum += e;
        }
    }

    if (lane == 0) s_wsum[warp] = wsum;
    __syncthreads();
    if (threadIdx.x == 0) {
        float s = 0.f;
#pragma unroll
        for (int w = 0; w < 8; w++) s += s_wsum[w];
        g_psum[b * NBLK + blockIdx.x] = s;
    }
}

// ---------------------------------------------------------------------------
// Kernel 3: normalize. grid (4, B) x 256 threads, barrier-free: every warp
// redundantly reduces the 128 L2-resident psums via shfl (4 loads/lane);
// no smem, no __syncthreads; the v-load overlaps the reduction.
// ---------------------------------------------------------------------------
__global__ void normalize_kernel(float* __restrict__ out) {
    const int b    = blockIdx.y;
    const int tid  = threadIdx.x;          // 0..255
    const int lane = tid & 31;

    cudaGridDependencySynchronize();

    // element this thread owns (independent of the reduction -> overlaps)
    const int idx = blockIdx.x * 256 + tid;   // float4 index within row b
    const float4* src = (const float4*)(g_scores + b * T);
    float4 v = src[idx];

    // per-warp redundant reduction of the 128 per-block partials
    float s = 0.f;
#pragma unroll
    for (int i = 0; i < 4; i++)
        s += g_psum[b * NBLK + lane + i * 32];
#pragma unroll
    for (int o = 16; o > 0; o >>= 1)
        s += __shfl_xor_sync(0xffffffffu, s, o);
    const float inv = 1.0f / s;

    float4* dst = (float4*)(out + b * T);
    v.x *= inv; v.y *= inv; v.z *= inv; v.w *= inv;
    dst[idx] = v;
}

// ---------------------------------------------------------------------------
// Host: PDL launches.
// ---------------------------------------------------------------------------
template <typename K, typename... Args>
static inline void launch_pdl(dim3 grid, dim3 block, K kern, Args... args) {
    cudaLaunchConfig_t cfg = {};
    cudaLaunchAttribute attr[1];
    attr[0].id = cudaLaunchAttributeProgrammaticStreamSerialization;
    attr[0].val.programmaticStreamSerializationAllowed = 1;
    cfg.gridDim = grid;
    cfg.blockDim = block;
    cfg.dynamicSmemBytes = 0;
    cfg.stream = 0;
    cfg.attrs = attr;
    cfg.numAttrs = 1;
    cudaLaunchKernelEx(&cfg, kern, args...);
}

extern "C" void kernel_launch(void* const* d_in, const int* in_sizes, int n_in,
                              void* d_out, int out_size) {
    const float* query = (const float*)d_in[0];   // [B, QS]
    const float* key   = (const float*)d_in[1];   // [B, T, KS]
    const float* mask  = (const float*)d_in[2];   // [B, T]
    const float* W     = (const float*)d_in[3];   // [KS, QS]
    const float* bias  = (const float*)d_in[4];   // [1]
    float* out = (float*)d_out;                   // [B, T]

    dim3 grid1(KS / 64, QSPLIT);
    mids_partial_kernel<<<grid1, 256>>>(query, W);

    launch_pdl(dim3((B * KS / 4) / 256), dim3(256), mids_reduce_kernel);

    launch_pdl(dim3(NBLK, B), dim3(256), scores_kernel, key, mask, bias);

    launch_pdl(dim3(T / 4 / 256, B), dim3(256), normalize_kernel, out);
}